// round 12
// baseline (speedup 1.0000x reference)
#include <cuda_runtime.h>
#include <cuda_fp16.h>
#include <cstddef>
#include <cstdint>

#define BB 8
#define CC 256
#define NN 2304            // 48*48

// ---------------- scratch (static device memory: allowed) ----------------
__device__ __align__(16) float g_s[(size_t)BB*NN*NN];   // 170 MB scores
__device__ __align__(16) float g_y[(size_t)BB*NN*CC];   // y in [b][n][o]
__device__ float g_mean[CC];
__device__ float g_rstd[CC];
__device__ float g_p1[48][CC];
__device__ float g_p2[48][CC];

// fp16 operands (hi/lo split where needed)
__device__ __align__(16) __half g_xth[(size_t)BB*NN*CC],  g_xtl[(size_t)BB*NN*CC];   // xT [b][n][c]
__device__ __align__(16) __half g_kqth[(size_t)BB*NN*512], g_kqtl[(size_t)BB*NN*512]; // [b][n][k|q]
__device__ __align__(16) __half g_v  [(size_t)BB*CC*NN];                              // v single fp16
__device__ __align__(16) __half g_at [(size_t)BB*NN*CC];                              // attnT single fp16
__device__ __align__(16) __half g_p  [(size_t)BB*NN*NN];                              // P single fp16
__device__ __align__(16) __half g_wkqh[2*CC*CC], g_wkql[2*CC*CC];  // [Wk;Wq]
__device__ __align__(16) __half g_wvh[CC*CC], g_wvl[CC*CC];
__device__ __align__(16) __half g_w2h[CC*CC], g_w2l[CC*CC];

// ---------------- helpers ----------------
__device__ __forceinline__ void split_h(float f, __half& h, __half& l) {
    h = __float2half_rn(f);
    l = __float2half_rn(f - __half2float(h));
}

__device__ __forceinline__ void ldsm4(uint32_t& r0, uint32_t& r1, uint32_t& r2, uint32_t& r3,
                                      const void* p) {
    uint32_t a = (uint32_t)__cvta_generic_to_shared(p);
    asm volatile("ldmatrix.sync.aligned.m8n8.x4.shared.b16 {%0,%1,%2,%3}, [%4];\n"
                 : "=r"(r0), "=r"(r1), "=r"(r2), "=r"(r3) : "r"(a));
}

__device__ __forceinline__ void mma16816(float* c, const uint32_t* a, const uint32_t* b) {
    asm volatile("mma.sync.aligned.m16n8k16.row.col.f32.f16.f16.f32 "
                 "{%0,%1,%2,%3}, {%4,%5,%6,%7}, {%8,%9}, {%0,%1,%2,%3};\n"
                 : "+f"(c[0]), "+f"(c[1]), "+f"(c[2]), "+f"(c[3])
                 : "r"(a[0]), "r"(a[1]), "r"(a[2]), "r"(a[3]), "r"(b[0]), "r"(b[1]));
}

__device__ __forceinline__ void cpasync16(void* s, const void* g) {
    uint32_t a = (uint32_t)__cvta_generic_to_shared(s);
    asm volatile("cp.async.cg.shared.global [%0], [%1], 16;\n" :: "r"(a), "l"(g));
}
__device__ __forceinline__ void cp_commit() { asm volatile("cp.async.commit_group;\n" ::); }

// =========================================================================
// split-fp16 tensor-core GEMM: D[b][M0+r][N0+c] = sum_k A[r][k]*B[c][k]
// TERMS bitmask: 1 = Ah*Bh (always), 2 = Ah*Bl, 4 = Al*Bh.
// Block tile 256(M) x 128(N), 512 threads (4x4 warps, warp tile 64x32),
// K-chunk 32, NSTAGES-deep cp.async pipeline (prefetch distance NSTAGES-1).
// Epilogue: fp32 (+bias) if Df; split fp16 if Dh&&Dl; single fp16 if Dh only.
// =========================================================================
template<int TERMS, int NSTAGES>
__global__ __launch_bounds__(512, 1) void mma_split_gemm(
    const __half* __restrict__ Ah, const __half* __restrict__ Al,
    size_t aBatch, int aStride,
    const __half* __restrict__ Bh, const __half* __restrict__ Bl,
    size_t bBatch, int bStride,
    float* __restrict__ Df,
    __half* __restrict__ Dh, __half* __restrict__ Dl,
    const float* __restrict__ bias,
    size_t dBatch, int dStride, int Ktot)
{
    constexpr int MT = 256;
    constexpr int ABUFS = (TERMS & 4) ? 2 : 1;
    constexpr int BBUFS = (TERMS & 2) ? 2 : 1;
    constexpr int ASZ = MT * 40;        // halfs per A buffer
    constexpr int BSZ = 128 * 40;       // halfs per B buffer
    constexpr int STG = ABUFS * ASZ + BBUFS * BSZ;

    extern __shared__ __align__(16) __half smem[];
#define AHH(s)  (smem + (s)*STG)
#define ALL_(s) (smem + (s)*STG + ASZ)
#define BHH(s)  (smem + (s)*STG + ABUFS*ASZ)
#define BLL(s)  (smem + (s)*STG + ABUFS*ASZ + BSZ)

    const int b  = blockIdx.z;
    const int M0 = blockIdx.y * MT;
    const int N0 = blockIdx.x * 128;
    const int tid  = threadIdx.x;
    const int lane = tid & 31;
    const int warp = tid >> 5;
    const int wm = warp >> 2;     // 0..3
    const int wn = warp & 3;      // 0..3

    const __half* Abh = Ah + (size_t)b*aBatch + (size_t)M0*aStride;
    const __half* Abl = (TERMS & 4) ? Al + (size_t)b*aBatch + (size_t)M0*aStride : nullptr;
    const __half* Bbh = Bh + (size_t)b*bBatch + (size_t)N0*bStride;
    const __half* Bbl = (TERMS & 2) ? Bl + (size_t)b*bBatch + (size_t)N0*bStride : nullptr;

    float acc[4][4][4];
#pragma unroll
    for (int i = 0; i < 4; i++)
#pragma unroll
        for (int j = 0; j < 4; j++)
#pragma unroll
            for (int r = 0; r < 4; r++) acc[i][j][r] = 0.f;

    const int T = Ktot >> 5;   // K chunks of 32

    // ---- stage loader: A rows MT, B rows 128, 8 halfs (16B) per cp ----
    auto load_stage = [&](int s, int k0) {
        // A hi (+lo): MT*4 = 1024 transfers over 512 threads
#pragma unroll
        for (int it = 0; it < MT*4/512; it++) {
            int e = tid + it*512;
            int row = e >> 2, seg = (e & 3) * 8;
            cpasync16(AHH(s)+row*40+seg, Abh + (size_t)row*aStride + k0 + seg);
            if (TERMS & 4) cpasync16(ALL_(s)+row*40+seg, Abl + (size_t)row*aStride + k0 + seg);
        }
        // B hi (+lo): 128*4 = 512 transfers
        {
            int e = tid;
            int row = e >> 2, seg = (e & 3) * 8;
            cpasync16(BHH(s)+row*40+seg, Bbh + (size_t)row*bStride + k0 + seg);
            if (TERMS & 2) cpasync16(BLL(s)+row*40+seg, Bbl + (size_t)row*bStride + k0 + seg);
        }
    };

    // prologue: load stages 0..NSTAGES-2
#pragma unroll
    for (int s = 0; s < NSTAGES-1; s++) { load_stage(s, s*32); cp_commit(); }

    int cur = 0, fill = NSTAGES - 1;
    for (int t = 0; t < T; t++) {
        if (NSTAGES == 3) asm volatile("cp.async.wait_group 1;\n" ::);
        else              asm volatile("cp.async.wait_group 2;\n" ::);
        __syncthreads();

        if (t + NSTAGES - 1 < T) load_stage(fill, (t + NSTAGES - 1) * 32);
        cp_commit();   // always commit (possibly empty) to keep group accounting fixed

#pragma unroll
        for (int kk = 0; kk < 32; kk += 16) {
            uint32_t Bfh[4][2], Bfl[4][2];
#pragma unroll
            for (int p = 0; p < 2; p++) {
                int r = wn*32 + p*16 + ((lane >> 4) << 3) + (lane & 7);
                int c = kk + (((lane >> 3) & 1) << 3);
                uint32_t r0, r1, r2, r3;
                ldsm4(r0, r1, r2, r3, BHH(cur)+r*40+c);
                Bfh[2*p][0] = r0; Bfh[2*p][1] = r1;
                Bfh[2*p+1][0] = r2; Bfh[2*p+1][1] = r3;
                if (TERMS & 2) {
                    ldsm4(r0, r1, r2, r3, BLL(cur)+r*40+c);
                    Bfl[2*p][0] = r0; Bfl[2*p][1] = r1;
                    Bfl[2*p+1][0] = r2; Bfl[2*p+1][1] = r3;
                }
            }
#pragma unroll
            for (int mi = 0; mi < 4; mi++) {
                int r = wm*64 + mi*16 + (lane & 15);
                int c = kk + ((lane >> 4) << 3);
                uint32_t Ahf[4], Alf[4];
                ldsm4(Ahf[0], Ahf[1], Ahf[2], Ahf[3], AHH(cur)+r*40+c);
                if (TERMS & 4) ldsm4(Alf[0], Alf[1], Alf[2], Alf[3], ALL_(cur)+r*40+c);
#pragma unroll
                for (int ni = 0; ni < 4; ni++) mma16816(acc[mi][ni], Ahf, Bfh[ni]);
                if (TERMS & 2) {
#pragma unroll
                    for (int ni = 0; ni < 4; ni++) mma16816(acc[mi][ni], Ahf, Bfl[ni]);
                }
                if (TERMS & 4) {
#pragma unroll
                    for (int ni = 0; ni < 4; ni++) mma16816(acc[mi][ni], Alf, Bfh[ni]);
                }
            }
        }
        cur = (cur + 1 == NSTAGES) ? 0 : cur + 1;
        fill = (fill + 1 == NSTAGES) ? 0 : fill + 1;
    }

    const int g = lane >> 2, tg2 = (lane & 3) * 2;
    if (Df) {
        float* Db = Df + (size_t)b*dBatch;
#pragma unroll
        for (int mi = 0; mi < 4; mi++)
#pragma unroll
            for (int ni = 0; ni < 4; ni++) {
                int row = M0 + wm*64 + mi*16 + g;
                int col = N0 + wn*32 + ni*8 + tg2;
                float b0 = bias ? bias[col] : 0.f;
                float b1 = bias ? bias[col+1] : 0.f;
                *(float2*)&Db[(size_t)row*dStride + col] =
                    make_float2(acc[mi][ni][0]+b0, acc[mi][ni][1]+b1);
                *(float2*)&Db[(size_t)(row+8)*dStride + col] =
                    make_float2(acc[mi][ni][2]+b0, acc[mi][ni][3]+b1);
            }
    } else if (Dl) {
        __half* Dbh = Dh + (size_t)b*dBatch;
        __half* Dbl = Dl + (size_t)b*dBatch;
#pragma unroll
        for (int mi = 0; mi < 4; mi++)
#pragma unroll
            for (int ni = 0; ni < 4; ni++) {
                int row = M0 + wm*64 + mi*16 + g;
                int col = N0 + wn*32 + ni*8 + tg2;
                __half h0,l0,h1,l1;
                split_h(acc[mi][ni][0], h0, l0);
                split_h(acc[mi][ni][1], h1, l1);
                *(__half2*)&Dbh[(size_t)row*dStride + col] = __halves2half2(h0, h1);
                *(__half2*)&Dbl[(size_t)row*dStride + col] = __halves2half2(l0, l1);
                split_h(acc[mi][ni][2], h0, l0);
                split_h(acc[mi][ni][3], h1, l1);
                *(__half2*)&Dbh[(size_t)(row+8)*dStride + col] = __halves2half2(h0, h1);
                *(__half2*)&Dbl[(size_t)(row+8)*dStride + col] = __halves2half2(l0, l1);
            }
    } else {
        __half* Dbh = Dh + (size_t)b*dBatch;
#pragma unroll
        for (int mi = 0; mi < 4; mi++)
#pragma unroll
            for (int ni = 0; ni < 4; ni++) {
                int row = M0 + wm*64 + mi*16 + g;
                int col = N0 + wn*32 + ni*8 + tg2;
                *(__half2*)&Dbh[(size_t)row*dStride + col] =
                    __halves2half2(__float2half_rn(acc[mi][ni][0]), __float2half_rn(acc[mi][ni][1]));
                *(__half2*)&Dbh[(size_t)(row+8)*dStride + col] =
                    __halves2half2(__float2half_rn(acc[mi][ni][2]), __float2half_rn(acc[mi][ni][3]));
            }
    }
#undef AHH
#undef ALL_
#undef BHH
#undef BLL
}

// =========================================================================
// merged weight split: Wk,Wq -> concatenated [Wk;Wq]; Wv, W2 separate
// =========================================================================
__global__ __launch_bounds__(256) void wsplit_all(
    const float* __restrict__ Wk, const float* __restrict__ Wq,
    const float* __restrict__ Wv, const float* __restrict__ W2)
{
    const int sel = blockIdx.y;
    const float* W = sel == 0 ? Wk : sel == 1 ? Wq : sel == 2 ? Wv : W2;
    __half* h = sel == 0 ? g_wkqh : sel == 1 ? (g_wkqh + CC*CC)
              : sel == 2 ? g_wvh : g_w2h;
    __half* l = sel == 0 ? g_wkql : sel == 1 ? (g_wkql + CC*CC)
              : sel == 2 ? g_wvl : g_w2l;
    int i = blockIdx.x * 256 + threadIdx.x;
    split_h(W[i], h[i], l[i]);
}

// =========================================================================
// x transpose + split: x [b][c][n] fp32 -> xT hi/lo [b][n][c]
// =========================================================================
__global__ __launch_bounds__(256) void xsplit_kernel(const float* __restrict__ x)
{
    __shared__ float Tm[32][33];
    const int b = blockIdx.z;
    const float* src = x + (size_t)b*CC*NN;
    __half* dh = g_xth + (size_t)b*NN*CC;
    __half* dl = g_xtl + (size_t)b*NN*CC;
    const int n0 = blockIdx.x * 32, c0 = blockIdx.y * 32;
    const int tx = threadIdx.x & 31, ty = threadIdx.x >> 5;

#pragma unroll
    for (int j = 0; j < 4; j++)
        Tm[ty + j*8][tx] = src[(size_t)(c0 + ty + j*8)*NN + n0 + tx];
    __syncthreads();
#pragma unroll
    for (int j = 0; j < 4; j++) {
        float v = Tm[tx][ty + j*8];
        int n = n0 + ty + j*8;
        __half h, l;
        split_h(v, h, l);
        dh[(size_t)n*CC + c0 + tx] = h;
        dl[(size_t)n*CC + c0 + tx] = l;
    }
}

// =========================================================================
// softmax over m of g_s; 288 threads x 8 contiguous elems; single fp16 P out
// =========================================================================
__global__ __launch_bounds__(288) void softmax_kernel()
{
    const int b = blockIdx.y, n = blockIdx.x;
    const float* row = g_s + ((size_t)b*NN + n) * NN;
    __half* pp = g_p + ((size_t)b*NN + n) * NN;
    const int tid = threadIdx.x;
    const int base = tid * 8;

    float4 a0 = *(const float4*)&row[base];
    float4 a1 = *(const float4*)&row[base + 4];
    float v[8] = {a0.x, a0.y, a0.z, a0.w, a1.x, a1.y, a1.z, a1.w};

    float mx = v[0];
#pragma unroll
    for (int i = 1; i < 8; i++) mx = fmaxf(mx, v[i]);

    __shared__ float red[9];
#pragma unroll
    for (int off = 16; off; off >>= 1) mx = fmaxf(mx, __shfl_xor_sync(0xffffffffu, mx, off));
    if ((tid & 31) == 0) red[tid >> 5] = mx;
    __syncthreads();
    float gmx = red[0];
#pragma unroll
    for (int i = 1; i < 9; i++) gmx = fmaxf(gmx, red[i]);

    float s = 0.f;
#pragma unroll
    for (int i = 0; i < 8; i++) { v[i] = __expf(v[i] - gmx); s += v[i]; }
    __syncthreads();
#pragma unroll
    for (int off = 16; off; off >>= 1) s += __shfl_xor_sync(0xffffffffu, s, off);
    if ((tid & 31) == 0) red[tid >> 5] = s;
    __syncthreads();
    float tot = 0.f;
#pragma unroll
    for (int i = 0; i < 9; i++) tot += red[i];
    float inv = 1.0f / tot;

    __align__(16) __half h8[8];
#pragma unroll
    for (int i = 0; i < 8; i++) h8[i] = __float2half_rn(v[i] * inv);
    *(uint4*)&pp[base] = *(uint4*)h8;
}

// =========================================================================
// BatchNorm stats over y [b][n][o], two-phase
// =========================================================================
__global__ __launch_bounds__(256) void bnstats_part()
{
    const int tx = threadIdx.x & 31, ty = threadIdx.x >> 5;
    const int o = blockIdx.x * 32 + tx;
    const int slab = blockIdx.y;
    const int nbase = slab * 48;
    float s1 = 0.f, s2 = 0.f;
#pragma unroll
    for (int b = 0; b < BB; b++) {
        const float* yb = g_y + (size_t)b*NN*CC;
#pragma unroll
        for (int j = 0; j < 6; j++) {
            float v = yb[(size_t)(nbase + ty + j*8)*CC + o];
            s1 += v; s2 += v*v;
        }
    }
    __shared__ float r1[8][33], r2[8][33];
    r1[ty][tx] = s1; r2[ty][tx] = s2;
    __syncthreads();
    if (ty == 0) {
        float S1 = s1, S2 = s2;
#pragma unroll
        for (int i = 1; i < 8; i++) { S1 += r1[i][tx]; S2 += r2[i][tx]; }
        g_p1[slab][o] = S1;
        g_p2[slab][o] = S2;
    }
}

__global__ __launch_bounds__(256) void bnstats_fin()
{
    const int o = threadIdx.x;
    float S1 = 0.f, S2 = 0.f;
#pragma unroll
    for (int s = 0; s < 48; s++) { S1 += g_p1[s][o]; S2 += g_p2[s][o]; }
    const float invM = 1.0f / (float)(BB*NN);
    float mean = S1 * invM;
    float var  = S2 * invM - mean*mean;
    g_mean[o] = mean;
    g_rstd[o] = rsqrtf(var + 1e-5f);
}

// =========================================================================
// normalize + affine + transpose: y [b][n][o] -> out [b][o][n]
// =========================================================================
__global__ __launch_bounds__(256) void bnorm_kernel(
    const float* __restrict__ gamma, const float* __restrict__ beta,
    float* __restrict__ out)
{
    __shared__ float Tm[32][33];
    const int b = blockIdx.z;
    const int n0 = blockIdx.x * 32, o0 = blockIdx.y * 32;
    const int tx = threadIdx.x & 31, ty = threadIdx.x >> 5;
    const float* yb = g_y + (size_t)b*NN*CC;
#pragma unroll
    for (int j = 0; j < 4; j++)
        Tm[ty + j*8][tx] = yb[(size_t)(n0 + ty + j*8)*CC + o0 + tx];
    __syncthreads();
#pragma unroll
    for (int j = 0; j < 4; j++) {
        int o = o0 + ty + j*8;
        float sc = g_rstd[o] * gamma[o];
        float mb = g_mean[o];
        out[((size_t)b*CC + o)*NN + n0 + tx] = (Tm[tx][ty + j*8] - mb) * sc + beta[o];
    }
}

// =========================================================================
extern "C" void kernel_launch(void* const* d_in, const int* in_sizes, int n_in,
                              void* d_out, int out_size)
{
    (void)in_sizes; (void)n_in; (void)out_size;
    const float* x     = (const float*)d_in[0];
    const float* Wk    = (const float*)d_in[1];
    const float* Wq    = (const float*)d_in[2];
    const float* Wv    = (const float*)d_in[3];
    const float* W2    = (const float*)d_in[4];
    const float* b2    = (const float*)d_in[5];
    const float* gamma = (const float*)d_in[6];
    const float* beta  = (const float*)d_in[7];
    float* out = (float*)d_out;

    float *ps, *py;
    __half *pxth,*pxtl,*pkqth,*pkqtl,*pv,*pat,*pp;
    __half *pwkqh,*pwkql,*pwvh,*pwvl,*pw2h,*pw2l;
    cudaGetSymbolAddress((void**)&ps,    g_s);
    cudaGetSymbolAddress((void**)&py,    g_y);
    cudaGetSymbolAddress((void**)&pxth,  g_xth);  cudaGetSymbolAddress((void**)&pxtl,  g_xtl);
    cudaGetSymbolAddress((void**)&pkqth, g_kqth); cudaGetSymbolAddress((void**)&pkqtl, g_kqtl);
    cudaGetSymbolAddress((void**)&pv,    g_v);
    cudaGetSymbolAddress((void**)&pat,   g_at);   cudaGetSymbolAddress((void**)&pp,    g_p);
    cudaGetSymbolAddress((void**)&pwkqh, g_wkqh); cudaGetSymbolAddress((void**)&pwkql, g_wkql);
    cudaGetSymbolAddress((void**)&pwvh,  g_wvh);  cudaGetSymbolAddress((void**)&pwvl,  g_wvl);
    cudaGetSymbolAddress((void**)&pw2h,  g_w2h);  cudaGetSymbolAddress((void**)&pw2l,  g_w2l);

    // dynamic smem sizes (bytes): stage = (ABUFS*256*40 + BBUFS*128*40)*2
    const int SM7 = 3 * (2*256*40 + 2*128*40) * 2;  // 184320  (TERMS=7, 3 stages)
    const int SM5 = 3 * (2*256*40 + 1*128*40) * 2;  // 153600  (TERMS=5, 3 stages)
    const int SM3 = 3 * (1*256*40 + 2*128*40) * 2;  // 122880  (TERMS=3, 3 stages)
    const int SM1 = 4 * (1*256*40 + 1*128*40) * 2;  // 122880  (TERMS=1, 4 stages)
    cudaFuncSetAttribute(mma_split_gemm<7,3>, cudaFuncAttributeMaxDynamicSharedMemorySize, SM7);
    cudaFuncSetAttribute(mma_split_gemm<5,3>, cudaFuncAttributeMaxDynamicSharedMemorySize, SM5);
    cudaFuncSetAttribute(mma_split_gemm<3,3>, cudaFuncAttributeMaxDynamicSharedMemorySize, SM3);
    cudaFuncSetAttribute(mma_split_gemm<1,4>, cudaFuncAttributeMaxDynamicSharedMemorySize, SM1);

    dim3 blk(256);
    dim3 blk512(512);

    wsplit_all<<<dim3(CC*CC/256, 4), blk>>>(Wk, Wq, Wv, W2);

    xsplit_kernel<<<dim3(NN/32, CC/32, BB), blk>>>(x);

    // kqT[b][n][o] = sum_c xT[n][c] * Wkq[o][c]  (3 terms, split out)
    mma_split_gemm<7,3><<<dim3(512/128, NN/256, BB), blk512, SM7>>>(
        pxth, pxtl, (size_t)NN*CC, CC,  pwkqh, pwkql, 0, CC,
        nullptr, pkqth, pkqtl, nullptr, (size_t)NN*512, 512, CC);

    // v[b][c][m] = sum_c' Wv[c][c'] * xT[m][c']  (2 terms: (Wh+Wl)*xh; single fp16 out)
    mma_split_gemm<5,3><<<dim3(NN/128, CC/256, BB), blk512, SM5>>>(
        pwvh, pwvl, 0, CC,  pxth, pxtl, (size_t)NN*CC, CC,
        nullptr, pv, nullptr, nullptr, (size_t)CC*NN, NN, CC);

    // scores[b][n][m] = sum_c kT[n][c]*qT[m][c]  (3 terms, fp32 out)
    mma_split_gemm<7,3><<<dim3(NN/128, NN/256, BB), blk512, SM7>>>(
        pkqth, pkqtl, (size_t)NN*512, 512,
        pkqth + CC, pkqtl + CC, (size_t)NN*512, 512,
        ps, nullptr, nullptr, nullptr, (size_t)NN*NN, NN, CC);

    softmax_kernel<<<dim3(NN, BB), 288>>>();

    // attnT[b][n][c] = sum_m P[n][m]*v[c][m]  (1 term: fp16 P x fp16 v)
    mma_split_gemm<1,4><<<dim3(CC/128, NN/256, BB), blk512, SM1>>>(
        pp, nullptr, (size_t)NN*NN, NN,  pv, nullptr, (size_t)CC*NN, NN,
        nullptr, pat, nullptr, nullptr, (size_t)NN*CC, CC, NN);

    // y[b][n][o] = sum_c attnT[n][c]*W2[o][c] + b2[o]  (2 terms; fp32 out)
    mma_split_gemm<3,3><<<dim3(CC/128, NN/256, BB), blk512, SM3>>>(
        pat, nullptr, (size_t)NN*CC, CC,  pw2h, pw2l, 0, CC,
        py, nullptr, nullptr, b2, (size_t)NN*CC, CC, CC);

    bnstats_part<<<dim3(CC/32, 48), blk>>>();
    bnstats_fin<<<1, CC>>>();

    bnorm_kernel<<<dim3(NN/32, CC/32, BB), blk>>>(gamma, beta, out);
}

// round 13
// speedup vs baseline: 1.0675x; 1.0675x over previous
#include <cuda_runtime.h>
#include <cuda_fp16.h>
#include <cstddef>
#include <cstdint>

#define BB 8
#define CC 256
#define NN 2304            // 48*48

// ---------------- scratch (static device memory: allowed) ----------------
__device__ __align__(16) float g_s[(size_t)BB*NN*NN];   // 170 MB scores
__device__ __align__(16) float g_y[(size_t)BB*NN*CC];   // y in [b][n][o]
__device__ float g_mean[CC];
__device__ float g_rstd[CC];
__device__ float g_p1[18][CC];   // per n-slab partial sums (filled by W2 epilogue)
__device__ float g_p2[18][CC];

// fp16 operands (hi/lo split where needed)
__device__ __align__(16) __half g_xth[(size_t)BB*NN*CC],  g_xtl[(size_t)BB*NN*CC];   // xT [b][n][c]
__device__ __align__(16) __half g_kqth[(size_t)BB*NN*512], g_kqtl[(size_t)BB*NN*512]; // [b][n][k|q]
__device__ __align__(16) __half g_v  [(size_t)BB*CC*NN];                              // v single fp16
__device__ __align__(16) __half g_at [(size_t)BB*NN*CC];                              // attnT single fp16
__device__ __align__(16) __half g_p  [(size_t)BB*NN*NN];                              // P single fp16
__device__ __align__(16) __half g_wkqh[2*CC*CC], g_wkql[2*CC*CC];  // [Wk;Wq]
__device__ __align__(16) __half g_wvh[CC*CC], g_wvl[CC*CC];
__device__ __align__(16) __half g_w2h[CC*CC], g_w2l[CC*CC];

// ---------------- helpers ----------------
__device__ __forceinline__ void split_h(float f, __half& h, __half& l) {
    h = __float2half_rn(f);
    l = __float2half_rn(f - __half2float(h));
}

__device__ __forceinline__ void ldsm4(uint32_t& r0, uint32_t& r1, uint32_t& r2, uint32_t& r3,
                                      const void* p) {
    uint32_t a = (uint32_t)__cvta_generic_to_shared(p);
    asm volatile("ldmatrix.sync.aligned.m8n8.x4.shared.b16 {%0,%1,%2,%3}, [%4];\n"
                 : "=r"(r0), "=r"(r1), "=r"(r2), "=r"(r3) : "r"(a));
}

__device__ __forceinline__ void mma16816(float* c, const uint32_t* a, const uint32_t* b) {
    asm volatile("mma.sync.aligned.m16n8k16.row.col.f32.f16.f16.f32 "
                 "{%0,%1,%2,%3}, {%4,%5,%6,%7}, {%8,%9}, {%0,%1,%2,%3};\n"
                 : "+f"(c[0]), "+f"(c[1]), "+f"(c[2]), "+f"(c[3])
                 : "r"(a[0]), "r"(a[1]), "r"(a[2]), "r"(a[3]), "r"(b[0]), "r"(b[1]));
}

__device__ __forceinline__ void cpasync16(void* s, const void* g) {
    uint32_t a = (uint32_t)__cvta_generic_to_shared(s);
    asm volatile("cp.async.cg.shared.global [%0], [%1], 16;\n" :: "r"(a), "l"(g));
}
__device__ __forceinline__ void cp_commit() { asm volatile("cp.async.commit_group;\n" ::); }

// =========================================================================
// split-fp16 tensor-core GEMM: D[b][M0+r][N0+c] = sum_k A[r][k]*B[c][k]
// TERMS bitmask: 1 = Ah*Bh (always), 2 = Ah*Bl, 4 = Al*Bh.
// Block tile 128x128, 256 threads (2x4 warps, warp tile 64x32), K-chunk 32,
// NSTAGES-deep cp.async pipeline, 2 CTAs/SM.
// STATS: if true (with Df), warp-reduce per-column sum/sumsq of the written
// tile and atomicAdd into g_p1/g_p2[blockIdx.y][col] (BN stats fusion).
// =========================================================================
template<int TERMS, int NSTAGES, bool STATS>
__global__ __launch_bounds__(256, 2) void mma_split_gemm(
    const __half* __restrict__ Ah, const __half* __restrict__ Al,
    size_t aBatch, int aStride,
    const __half* __restrict__ Bh, const __half* __restrict__ Bl,
    size_t bBatch, int bStride,
    float* __restrict__ Df,
    __half* __restrict__ Dh, __half* __restrict__ Dl,
    const float* __restrict__ bias,
    size_t dBatch, int dStride, int Ktot)
{
    constexpr int ABUFS = (TERMS & 4) ? 2 : 1;
    constexpr int BBUFS = (TERMS & 2) ? 2 : 1;
    constexpr int ASZ = 128 * 40;
    constexpr int BSZ = 128 * 40;
    constexpr int STG = ABUFS * ASZ + BBUFS * BSZ;

    extern __shared__ __align__(16) __half smem[];
#define AHH(s)  (smem + (s)*STG)
#define ALL_(s) (smem + (s)*STG + ASZ)
#define BHH(s)  (smem + (s)*STG + ABUFS*ASZ)
#define BLL(s)  (smem + (s)*STG + ABUFS*ASZ + BSZ)

    const int b  = blockIdx.z;
    const int M0 = blockIdx.y * 128;
    const int N0 = blockIdx.x * 128;
    const int tid  = threadIdx.x;
    const int lane = tid & 31;
    const int warp = tid >> 5;
    const int wm = warp >> 2;     // 0..1
    const int wn = warp & 3;      // 0..3

    const __half* Abh = Ah + (size_t)b*aBatch + (size_t)M0*aStride;
    const __half* Abl = (TERMS & 4) ? Al + (size_t)b*aBatch + (size_t)M0*aStride : nullptr;
    const __half* Bbh = Bh + (size_t)b*bBatch + (size_t)N0*bStride;
    const __half* Bbl = (TERMS & 2) ? Bl + (size_t)b*bBatch + (size_t)N0*bStride : nullptr;

    float acc[4][4][4];
#pragma unroll
    for (int i = 0; i < 4; i++)
#pragma unroll
        for (int j = 0; j < 4; j++)
#pragma unroll
            for (int r = 0; r < 4; r++) acc[i][j][r] = 0.f;

    const int T = Ktot >> 5;   // K chunks of 32

    auto load_stage = [&](int s, int k0) {
#pragma unroll
        for (int it = 0; it < 2; it++) {
            int e = tid + it*256;
            int row = e >> 2, seg = (e & 3) * 8;
            cpasync16(AHH(s)+row*40+seg, Abh + (size_t)row*aStride + k0 + seg);
            if (TERMS & 4) cpasync16(ALL_(s)+row*40+seg, Abl + (size_t)row*aStride + k0 + seg);
            cpasync16(BHH(s)+row*40+seg, Bbh + (size_t)row*bStride + k0 + seg);
            if (TERMS & 2) cpasync16(BLL(s)+row*40+seg, Bbl + (size_t)row*bStride + k0 + seg);
        }
    };

    // prologue: stages 0..NSTAGES-2
#pragma unroll
    for (int s = 0; s < NSTAGES-1; s++) { load_stage(s, s*32); cp_commit(); }

    int cur = 0, fill = NSTAGES - 1;
    for (int t = 0; t < T; t++) {
        asm volatile("cp.async.wait_group %0;\n" :: "n"(NSTAGES-2));
        __syncthreads();

        if (t + NSTAGES - 1 < T) load_stage(fill, (t + NSTAGES - 1) * 32);
        cp_commit();   // commit every iteration (possibly empty) for fixed accounting

#pragma unroll
        for (int kk = 0; kk < 32; kk += 16) {
            uint32_t Bfh[4][2], Bfl[4][2];
#pragma unroll
            for (int p = 0; p < 2; p++) {
                int r = wn*32 + p*16 + ((lane >> 4) << 3) + (lane & 7);
                int c = kk + (((lane >> 3) & 1) << 3);
                uint32_t r0, r1, r2, r3;
                ldsm4(r0, r1, r2, r3, BHH(cur)+r*40+c);
                Bfh[2*p][0] = r0; Bfh[2*p][1] = r1;
                Bfh[2*p+1][0] = r2; Bfh[2*p+1][1] = r3;
                if (TERMS & 2) {
                    ldsm4(r0, r1, r2, r3, BLL(cur)+r*40+c);
                    Bfl[2*p][0] = r0; Bfl[2*p][1] = r1;
                    Bfl[2*p+1][0] = r2; Bfl[2*p+1][1] = r3;
                }
            }
#pragma unroll
            for (int mi = 0; mi < 4; mi++) {
                int r = wm*64 + mi*16 + (lane & 15);
                int c = kk + ((lane >> 4) << 3);
                uint32_t Ahf[4], Alf[4];
                ldsm4(Ahf[0], Ahf[1], Ahf[2], Ahf[3], AHH(cur)+r*40+c);
                if (TERMS & 4) ldsm4(Alf[0], Alf[1], Alf[2], Alf[3], ALL_(cur)+r*40+c);
#pragma unroll
                for (int ni = 0; ni < 4; ni++) mma16816(acc[mi][ni], Ahf, Bfh[ni]);
                if (TERMS & 2) {
#pragma unroll
                    for (int ni = 0; ni < 4; ni++) mma16816(acc[mi][ni], Ahf, Bfl[ni]);
                }
                if (TERMS & 4) {
#pragma unroll
                    for (int ni = 0; ni < 4; ni++) mma16816(acc[mi][ni], Alf, Bfh[ni]);
                }
            }
        }
        cur = (cur + 1 == NSTAGES) ? 0 : cur + 1;
        fill = (fill + 1 == NSTAGES) ? 0 : fill + 1;
    }

    const int g = lane >> 2, tg2 = (lane & 3) * 2;
    if (Df) {
        float* Db = Df + (size_t)b*dBatch;
        float s1[4][2], s2[4][2];   // per (ni, col-in-pair) local sums over 8 rows
        if (STATS) {
#pragma unroll
            for (int ni = 0; ni < 4; ni++) { s1[ni][0]=s1[ni][1]=s2[ni][0]=s2[ni][1]=0.f; }
        }
#pragma unroll
        for (int mi = 0; mi < 4; mi++)
#pragma unroll
            for (int ni = 0; ni < 4; ni++) {
                int row = M0 + wm*64 + mi*16 + g;
                int col = N0 + wn*32 + ni*8 + tg2;
                float b0 = bias ? bias[col] : 0.f;
                float b1 = bias ? bias[col+1] : 0.f;
                float v0 = acc[mi][ni][0]+b0, v1 = acc[mi][ni][1]+b1;
                float v2 = acc[mi][ni][2]+b0, v3 = acc[mi][ni][3]+b1;
                *(float2*)&Db[(size_t)row*dStride + col]     = make_float2(v0, v1);
                *(float2*)&Db[(size_t)(row+8)*dStride + col] = make_float2(v2, v3);
                if (STATS) {
                    s1[ni][0] += v0 + v2;  s1[ni][1] += v1 + v3;
                    s2[ni][0] += v0*v0 + v2*v2;  s2[ni][1] += v1*v1 + v3*v3;
                }
            }
        if (STATS) {
            // reduce over the 8 g-lanes (same col); then lanes 0-3 do atomics
#pragma unroll
            for (int ni = 0; ni < 4; ni++)
#pragma unroll
                for (int cix = 0; cix < 2; cix++) {
#pragma unroll
                    for (int off = 16; off >= 4; off >>= 1) {
                        s1[ni][cix] += __shfl_xor_sync(0xffffffffu, s1[ni][cix], off);
                        s2[ni][cix] += __shfl_xor_sync(0xffffffffu, s2[ni][cix], off);
                    }
                }
            if (lane < 4) {
                const int slab = blockIdx.y;
#pragma unroll
                for (int ni = 0; ni < 4; ni++) {
                    int col = N0 + wn*32 + ni*8 + lane*2;
                    atomicAdd(&g_p1[slab][col],   s1[ni][0]);
                    atomicAdd(&g_p2[slab][col],   s2[ni][0]);
                    atomicAdd(&g_p1[slab][col+1], s1[ni][1]);
                    atomicAdd(&g_p2[slab][col+1], s2[ni][1]);
                }
            }
        }
    } else if (Dl) {
        __half* Dbh = Dh + (size_t)b*dBatch;
        __half* Dbl = Dl + (size_t)b*dBatch;
#pragma unroll
        for (int mi = 0; mi < 4; mi++)
#pragma unroll
            for (int ni = 0; ni < 4; ni++) {
                int row = M0 + wm*64 + mi*16 + g;
                int col = N0 + wn*32 + ni*8 + tg2;
                __half h0,l0,h1,l1;
                split_h(acc[mi][ni][0], h0, l0);
                split_h(acc[mi][ni][1], h1, l1);
                *(__half2*)&Dbh[(size_t)row*dStride + col] = __halves2half2(h0, h1);
                *(__half2*)&Dbl[(size_t)row*dStride + col] = __halves2half2(l0, l1);
                split_h(acc[mi][ni][2], h0, l0);
                split_h(acc[mi][ni][3], h1, l1);
                *(__half2*)&Dbh[(size_t)(row+8)*dStride + col] = __halves2half2(h0, h1);
                *(__half2*)&Dbl[(size_t)(row+8)*dStride + col] = __halves2half2(l0, l1);
            }
    } else {
        __half* Dbh = Dh + (size_t)b*dBatch;
#pragma unroll
        for (int mi = 0; mi < 4; mi++)
#pragma unroll
            for (int ni = 0; ni < 4; ni++) {
                int row = M0 + wm*64 + mi*16 + g;
                int col = N0 + wn*32 + ni*8 + tg2;
                *(__half2*)&Dbh[(size_t)row*dStride + col] =
                    __halves2half2(__float2half_rn(acc[mi][ni][0]), __float2half_rn(acc[mi][ni][1]));
                *(__half2*)&Dbh[(size_t)(row+8)*dStride + col] =
                    __halves2half2(__float2half_rn(acc[mi][ni][2]), __float2half_rn(acc[mi][ni][3]));
            }
    }
#undef AHH
#undef ALL_
#undef BHH
#undef BLL
}

// =========================================================================
// merged weight split + stat-buffer zeroing
// =========================================================================
__global__ __launch_bounds__(256) void wsplit_all(
    const float* __restrict__ Wk, const float* __restrict__ Wq,
    const float* __restrict__ Wv, const float* __restrict__ W2)
{
    const int sel = blockIdx.y;
    const float* W = sel == 0 ? Wk : sel == 1 ? Wq : sel == 2 ? Wv : W2;
    __half* h = sel == 0 ? g_wkqh : sel == 1 ? (g_wkqh + CC*CC)
              : sel == 2 ? g_wvh : g_w2h;
    __half* l = sel == 0 ? g_wkql : sel == 1 ? (g_wkql + CC*CC)
              : sel == 2 ? g_wvl : g_w2l;
    int i = blockIdx.x * 256 + threadIdx.x;
    split_h(W[i], h[i], l[i]);
    // zero BN partial buffers (18*256 floats each; grid.x*grid.y covers it)
    int z = (blockIdx.y * gridDim.x + blockIdx.x) * 256 + threadIdx.x;
    if (z < 18*CC) { (&g_p1[0][0])[z] = 0.f; (&g_p2[0][0])[z] = 0.f; }
}

// =========================================================================
// x transpose + split: x [b][c][n] fp32 -> xT hi/lo [b][n][c]
// =========================================================================
__global__ __launch_bounds__(256) void xsplit_kernel(const float* __restrict__ x)
{
    __shared__ float Tm[32][33];
    const int b = blockIdx.z;
    const float* src = x + (size_t)b*CC*NN;
    __half* dh = g_xth + (size_t)b*NN*CC;
    __half* dl = g_xtl + (size_t)b*NN*CC;
    const int n0 = blockIdx.x * 32, c0 = blockIdx.y * 32;
    const int tx = threadIdx.x & 31, ty = threadIdx.x >> 5;

#pragma unroll
    for (int j = 0; j < 4; j++)
        Tm[ty + j*8][tx] = src[(size_t)(c0 + ty + j*8)*NN + n0 + tx];
    __syncthreads();
#pragma unroll
    for (int j = 0; j < 4; j++) {
        float v = Tm[tx][ty + j*8];
        int n = n0 + ty + j*8;
        __half h, l;
        split_h(v, h, l);
        dh[(size_t)n*CC + c0 + tx] = h;
        dl[(size_t)n*CC + c0 + tx] = l;
    }
}

// =========================================================================
// softmax over m of g_s; 288 threads x 8 contiguous elems; single fp16 P out
// =========================================================================
__global__ __launch_bounds__(288) void softmax_kernel()
{
    const int b = blockIdx.y, n = blockIdx.x;
    const float* row = g_s + ((size_t)b*NN + n) * NN;
    __half* pp = g_p + ((size_t)b*NN + n) * NN;
    const int tid = threadIdx.x;
    const int base = tid * 8;

    float4 a0 = *(const float4*)&row[base];
    float4 a1 = *(const float4*)&row[base + 4];
    float v[8] = {a0.x, a0.y, a0.z, a0.w, a1.x, a1.y, a1.z, a1.w};

    float mx = v[0];
#pragma unroll
    for (int i = 1; i < 8; i++) mx = fmaxf(mx, v[i]);

    __shared__ float red[9];
#pragma unroll
    for (int off = 16; off; off >>= 1) mx = fmaxf(mx, __shfl_xor_sync(0xffffffffu, mx, off));
    if ((tid & 31) == 0) red[tid >> 5] = mx;
    __syncthreads();
    float gmx = red[0];
#pragma unroll
    for (int i = 1; i < 9; i++) gmx = fmaxf(gmx, red[i]);

    float s = 0.f;
#pragma unroll
    for (int i = 0; i < 8; i++) { v[i] = __expf(v[i] - gmx); s += v[i]; }
    __syncthreads();
#pragma unroll
    for (int off = 16; off; off >>= 1) s += __shfl_xor_sync(0xffffffffu, s, off);
    if ((tid & 31) == 0) red[tid >> 5] = s;
    __syncthreads();
    float tot = 0.f;
#pragma unroll
    for (int i = 0; i < 9; i++) tot += red[i];
    float inv = 1.0f / tot;

    __align__(16) __half h8[8];
#pragma unroll
    for (int i = 0; i < 8; i++) h8[i] = __float2half_rn(v[i] * inv);
    *(uint4*)&pp[base] = *(uint4*)h8;
}

// =========================================================================
// BN finalize from W2-epilogue partials
// =========================================================================
__global__ __launch_bounds__(256) void bnstats_fin()
{
    const int o = threadIdx.x;
    float S1 = 0.f, S2 = 0.f;
#pragma unroll
    for (int s = 0; s < 18; s++) { S1 += g_p1[s][o]; S2 += g_p2[s][o]; }
    const float invM = 1.0f / (float)(BB*NN);
    float mean = S1 * invM;
    float var  = S2 * invM - mean*mean;
    g_mean[o] = mean;
    g_rstd[o] = rsqrtf(var + 1e-5f);
}

// =========================================================================
// normalize + affine + transpose: y [b][n][o] -> out [b][o][n]
// =========================================================================
__global__ __launch_bounds__(256) void bnorm_kernel(
    const float* __restrict__ gamma, const float* __restrict__ beta,
    float* __restrict__ out)
{
    __shared__ float Tm[32][33];
    const int b = blockIdx.z;
    const int n0 = blockIdx.x * 32, o0 = blockIdx.y * 32;
    const int tx = threadIdx.x & 31, ty = threadIdx.x >> 5;
    const float* yb = g_y + (size_t)b*NN*CC;
#pragma unroll
    for (int j = 0; j < 4; j++)
        Tm[ty + j*8][tx] = yb[(size_t)(n0 + ty + j*8)*CC + o0 + tx];
    __syncthreads();
#pragma unroll
    for (int j = 0; j < 4; j++) {
        int o = o0 + ty + j*8;
        float sc = g_rstd[o] * gamma[o];
        float mb = g_mean[o];
        out[((size_t)b*CC + o)*NN + n0 + tx] = (Tm[tx][ty + j*8] - mb) * sc + beta[o];
    }
}

// =========================================================================
extern "C" void kernel_launch(void* const* d_in, const int* in_sizes, int n_in,
                              void* d_out, int out_size)
{
    (void)in_sizes; (void)n_in; (void)out_size;
    const float* x     = (const float*)d_in[0];
    const float* Wk    = (const float*)d_in[1];
    const float* Wq    = (const float*)d_in[2];
    const float* Wv    = (const float*)d_in[3];
    const float* W2    = (const float*)d_in[4];
    const float* b2    = (const float*)d_in[5];
    const float* gamma = (const float*)d_in[6];
    const float* beta  = (const float*)d_in[7];
    float* out = (float*)d_out;

    float *ps, *py;
    __half *pxth,*pxtl,*pkqth,*pkqtl,*pv,*pat,*pp;
    __half *pwkqh,*pwkql,*pwvh,*pwvl,*pw2h,*pw2l;
    cudaGetSymbolAddress((void**)&ps,    g_s);
    cudaGetSymbolAddress((void**)&py,    g_y);
    cudaGetSymbolAddress((void**)&pxth,  g_xth);  cudaGetSymbolAddress((void**)&pxtl,  g_xtl);
    cudaGetSymbolAddress((void**)&pkqth, g_kqth); cudaGetSymbolAddress((void**)&pkqtl, g_kqtl);
    cudaGetSymbolAddress((void**)&pv,    g_v);
    cudaGetSymbolAddress((void**)&pat,   g_at);   cudaGetSymbolAddress((void**)&pp,    g_p);
    cudaGetSymbolAddress((void**)&pwkqh, g_wkqh); cudaGetSymbolAddress((void**)&pwkql, g_wkql);
    cudaGetSymbolAddress((void**)&pwvh,  g_wvh);  cudaGetSymbolAddress((void**)&pwvl,  g_wvl);
    cudaGetSymbolAddress((void**)&pw2h,  g_w2h);  cudaGetSymbolAddress((void**)&pw2l,  g_w2l);

    // stage bytes = (ABUFS+BBUFS)*128*40*2 ; fit 2 CTAs/SM (<=114KB each)
    const int SM7 = 2 * (4*128*40) * 2;  // 81920   (TERMS=7, 2 stages)
    const int SM5 = 3 * (3*128*40) * 2;  // 92160   (TERMS=5, 3 stages)
    const int SM3 = 3 * (3*128*40) * 2;  // 92160   (TERMS=3, 3 stages)
    const int SM1 = 4 * (2*128*40) * 2;  // 81920   (TERMS=1, 4 stages)
    cudaFuncSetAttribute(mma_split_gemm<7,2,false>, cudaFuncAttributeMaxDynamicSharedMemorySize, SM7);
    cudaFuncSetAttribute(mma_split_gemm<5,3,false>, cudaFuncAttributeMaxDynamicSharedMemorySize, SM5);
    cudaFuncSetAttribute(mma_split_gemm<3,3,true>,  cudaFuncAttributeMaxDynamicSharedMemorySize, SM3);
    cudaFuncSetAttribute(mma_split_gemm<1,4,false>, cudaFuncAttributeMaxDynamicSharedMemorySize, SM1);

    dim3 blk(256);

    wsplit_all<<<dim3(CC*CC/256, 4), blk>>>(Wk, Wq, Wv, W2);

    xsplit_kernel<<<dim3(NN/32, CC/32, BB), blk>>>(x);

    // kqT[b][n][o] = sum_c xT[n][c] * Wkq[o][c]  (3 terms, split out)
    mma_split_gemm<7,2,false><<<dim3(512/128, NN/128, BB), blk, SM7>>>(
        pxth, pxtl, (size_t)NN*CC, CC,  pwkqh, pwkql, 0, CC,
        nullptr, pkqth, pkqtl, nullptr, (size_t)NN*512, 512, CC);

    // v[b][c][m] = sum_c' Wv[c][c'] * xT[m][c']  (2 terms; single fp16 out)
    mma_split_gemm<5,3,false><<<dim3(NN/128, CC/128, BB), blk, SM5>>>(
        pwvh, pwvl, 0, CC,  pxth, pxtl, (size_t)NN*CC, CC,
        nullptr, pv, nullptr, nullptr, (size_t)CC*NN, NN, CC);

    // scores[b][n][m] = sum_c kT[n][c]*qT[m][c]  (3 terms, fp32 out)
    mma_split_gemm<7,2,false><<<dim3(NN/128, NN/128, BB), blk, SM7>>>(
        pkqth, pkqtl, (size_t)NN*512, 512,
        pkqth + CC, pkqtl + CC, (size_t)NN*512, 512,
        ps, nullptr, nullptr, nullptr, (size_t)NN*NN, NN, CC);

    softmax_kernel<<<dim3(NN, BB), 288>>>();

    // attnT[b][n][c] = sum_m P[n][m]*v[c][m]  (1 term: fp16 P x fp16 v)
    mma_split_gemm<1,4,false><<<dim3(CC/128, NN/128, BB), blk, SM1>>>(
        pp, nullptr, (size_t)NN*NN, NN,  pv, nullptr, (size_t)CC*NN, NN,
        nullptr, pat, nullptr, nullptr, (size_t)NN*CC, CC, NN);

    // y[b][n][o] = sum_c attnT[n][c]*W2[o][c] + b2[o]  (2 terms; fp32 out + BN stats)
    mma_split_gemm<3,3,true><<<dim3(CC/128, NN/128, BB), blk, SM3>>>(
        pat, nullptr, (size_t)NN*CC, CC,  pw2h, pw2l, 0, CC,
        py, nullptr, nullptr, b2, (size_t)NN*CC, CC, CC);

    bnstats_fin<<<1, CC>>>();

    bnorm_kernel<<<dim3(NN/32, CC/32, BB), blk>>>(gamma, beta, out);
}